// round 16
// baseline (speedup 1.0000x reference)
#include <cuda_runtime.h>
#include <cuda_fp16.h>
#include <cstdint>
#include <cstddef>

#define T_SEQ 512
#define BATCH 64
#define DIN   256
#define HID   1024
#define NREC  256   // recurrence CTAs (2 per SM)

// ---------------- static scratch (no allocations) ----------------
__device__ __align__(16) float  g_xg[(size_t)T_SEQ * BATCH * 4096];    // [t][b][4H] fp32
__device__ __align__(16) __half g_seq0h[(size_t)T_SEQ * BATCH * HID];  // [t][b][k] fp16
__device__ __align__(16) __half g_x16[(size_t)BATCH * T_SEQ * DIN];    // x as fp16
__device__ __align__(16) __half g_w0_16[(size_t)4096 * DIN];           // Wih0 fp16
__device__ __align__(16) __half g_w1_16[(size_t)4096 * HID];           // Wih1 fp16
// h HISTORY (not ping-pong): step t's h lives at g_hist16[t] -> fresh addresses
// every step => L1-cached reads can never be stale. fp16 pairs, PAIR-INTERLEAVED
// m16n8k16-fragment order: u32 slot = kt*512 + (m*4 + tq)*2 + sub
__device__ __align__(16) unsigned g_hist16[T_SEQ + 1][(HID / 16) * 512];
__device__ unsigned g_bar;

// ---------------- helpers ----------------
__device__ __forceinline__ unsigned pack2(float x, float y) {
    __half2 h = __floats2half2_rn(x, y);
    return *reinterpret_cast<unsigned*>(&h);
}

__device__ __forceinline__ void mma_f16(float c[4], const uint32_t a[4], const uint32_t b[2]) {
    asm volatile(
        "mma.sync.aligned.m16n8k16.row.col.f32.f16.f16.f32 "
        "{%0,%1,%2,%3}, {%4,%5,%6,%7}, {%8,%9}, {%0,%1,%2,%3};"
        : "+f"(c[0]), "+f"(c[1]), "+f"(c[2]), "+f"(c[3])
        : "r"(a[0]), "r"(a[1]), "r"(a[2]), "r"(a[3]), "r"(b[0]), "r"(b[1]));
}

// ---------------- reset: zero h[0] + grid barrier ----------------
__global__ void reset_kernel() {
    int tid = blockIdx.x * blockDim.x + threadIdx.x;
    for (int i = tid; i < (HID / 16) * 512; i += gridDim.x * blockDim.x)
        g_hist16[0][i] = 0u;
    if (tid == 0) g_bar = 0u;
}

// ---------------- one-time fp32 -> fp16 conversion ----------------
// WHICH: 0 = Wih0 (4096*DIN), 1 = Wih1 (4096*HID), 2 = x (BATCH*T_SEQ*DIN)
template<int WHICH>
__global__ void f2h_kernel(const float* __restrict__ src, int n) {
    __half* dst = (WHICH == 0) ? g_w0_16 : (WHICH == 1) ? g_w1_16 : g_x16;
    int tid = blockIdx.x * blockDim.x + threadIdx.x;
    for (int i = tid; i < n; i += gridDim.x * blockDim.x)
        dst[i] = __float2half_rn(src[i]);
}

// ---------------- xg GEMM (fp16 inputs, M=128: 2 timesteps per CTA) ----------------
// AMODE 0: A = g_x16 [B][T][D] fp16,      W = g_w0_16, K = DIN
// AMODE 1: A = g_seq0h [T][B][H] fp16,    W = g_w1_16, K = HID
template<int AMODE>
__global__ __launch_bounds__(256) void gemm_xg(const float* __restrict__ bias, int K)
{
    __shared__ __align__(16) unsigned Ash[128 * 20];   // u32 = half2 pairs along k, stride 20
    __shared__ __align__(16) unsigned Bsh[128 * 20];

    const __half* A16 = (AMODE == 0) ? g_x16 : g_seq0h;
    const __half* W16 = (AMODE == 0) ? g_w0_16 : g_w1_16;

    const int tid = threadIdx.x, lane = tid & 31, w = tid >> 5;
    const int wm = w & 1, wn = w >> 1;          // 2 x 4 warp grid
    const int t0 = blockIdx.y * 2, n0 = blockIdx.x * 128;
    const int g = lane >> 2, tq = lane & 3;

    float acc[4][4][4] = {};

    const int nchunk = K / 32;
    for (int kc = 0; kc < nchunk; kc++) {
        int k0 = kc * 32;
        __syncthreads();
        // stage A: 128 rows x 32 k (uint4 = 8 halves)
        #pragma unroll
        for (int i = 0; i < 2; i++) {
            int fi = tid + i * 256; int r = fi >> 2, q = fi & 3;
            int tl = r >> 6, b = r & 63;
            size_t off = (AMODE == 0)
                ? ((size_t)b * T_SEQ + t0 + tl) * DIN + k0 + q * 8
                : ((size_t)(t0 + tl) * BATCH + b) * HID + k0 + q * 8;
            uint4 v = *(const uint4*)(A16 + off);
            *(uint4*)(Ash + r * 20 + q * 4) = v;
        }
        // stage B: 128 rows x 32 k
        #pragma unroll
        for (int i = 0; i < 2; i++) {
            int fi = tid + i * 256; int r = fi >> 2, q = fi & 3;
            uint4 v = *(const uint4*)(W16 + (size_t)(n0 + r) * K + k0 + q * 8);
            *(uint4*)(Bsh + r * 20 + q * 4) = v;
        }
        __syncthreads();
        #pragma unroll
        for (int kt = 0; kt < 2; kt++) {
            uint32_t a[4][4];
            #pragma unroll
            for (int am = 0; am < 4; am++) {
                int mb = wm * 64 + am * 16;
                a[am][0] = Ash[(mb + g) * 20 + kt * 8 + tq];
                a[am][1] = Ash[(mb + 8 + g) * 20 + kt * 8 + tq];
                a[am][2] = Ash[(mb + g) * 20 + kt * 8 + tq + 4];
                a[am][3] = Ash[(mb + 8 + g) * 20 + kt * 8 + tq + 4];
            }
            #pragma unroll
            for (int c = 0; c < 4; c++) {
                int nb = (wn * 4 + c) * 8;
                uint32_t b[2];
                b[0] = Bsh[(nb + g) * 20 + kt * 8 + tq];
                b[1] = Bsh[(nb + g) * 20 + kt * 8 + tq + 4];
                #pragma unroll
                for (int am = 0; am < 4; am++) mma_f16(acc[am][c], a[am], b);
            }
        }
    }
    #pragma unroll
    for (int am = 0; am < 4; am++) {
        int m = wm * 64 + am * 16 + g;
        int tl = m >> 6, b = m & 63;
        #pragma unroll
        for (int c = 0; c < 4; c++) {
            int n = n0 + (wn * 4 + c) * 8 + 2 * tq;
            float2 bi = *(const float2*)(bias + n);
            *(float2*)(g_xg + ((size_t)(t0 + tl) * BATCH + b) * 4096 + n) =
                make_float2(acc[am][c][0] + bi.x, acc[am][c][1] + bi.y);
            *(float2*)(g_xg + ((size_t)(t0 + tl) * BATCH + b + 8) * 4096 + n) =
                make_float2(acc[am][c][2] + bi.x, acc[am][c][3] + bi.y);
        }
    }
}

// ---------------- persistent LSTM recurrence (fp16 mma, 2 CTAs/SM) ----------------
// 256 CTAs x 256 threads. CTA owns 4 hidden units j0..j0+3 -> 16 gate rows.
// 8 warps = wm(2: batch halves) x wk(4: k-split of 16 k16-tiles each).
// h read from g_hist16[t] with L1-CACHED loads (fresh addresses each step -> never
// stale; the 2 co-resident CTAs/SM share h lines through L1, halving L2 traffic).
template<int LAYER>
__global__ __launch_bounds__(256, 2) void lstm_rec(const float* __restrict__ Whh)
{
    extern __shared__ __align__(16) char smraw[];
    uint2* Bsm = (uint2*)smraw;                       // 64kt x 2c x 32lane uint2 = 32 KB
    float* Gsm = (float*)(smraw + 32768);             // 4 slices x 64 x 20

    const int tid = threadIdx.x, lane = tid & 31, w = tid >> 5;
    const int g = lane >> 2, tq = lane & 3;
    const int wm = w & 1;            // batch half
    const int wk = w >> 1;           // 0..3 : k-split (16 k16-tiles each)
    const int bx = blockIdx.x;
    const int j0 = bx * 4;

    // load 16 weight rows (nrow = gate*4 + jj) -> SMEM in B-fragment order
    unsigned* Wsm32 = (unsigned*)smraw;
    #pragma unroll
    for (int i = 0; i < 16; i++) {
        int fi = tid + i * 256;               // float4 index 0..4095
        int r = fi >> 8, c4 = fi & 255;       // r = nrow ; k0 = c4*4
        int gate = r >> 2, jj = r & 3;
        float4 v = *(const float4*)(Whh + (size_t)(gate * HID + j0 + jj) * HID + c4 * 4);
        int kt = c4 >> 2, sub = (c4 >> 1) & 1, tq0 = (c4 & 1) * 2;
        int base = ((kt * 2 + (r >> 3)) * 32 + (r & 7) * 4 + tq0) * 2 + sub;
        Wsm32[base]     = pack2(v.x, v.y);
        Wsm32[base + 2] = pack2(v.z, v.w);
    }

    const int ejj = tid & 3, eb = tid >> 2;   // elementwise mapping: 256 threads = 64b x 4jj
    // producer u32 slot for k = j0+ejj:
    const int ktp = bx >> 2, subp = (bx >> 1) & 1, tqp = (bx & 1) * 2 + (ejj >> 1);
    const size_t hslot = (size_t)ktp * 512 + ((size_t)eb * 4 + tqp) * 2 + subp;
    float cst = 0.0f;
    __syncthreads();

    // prefetch xg for t=0
    const float* xgp = g_xg + (size_t)eb * 4096 + j0 + ejj;
    float x0 = __ldcs(xgp), x1 = __ldcs(xgp + 1024),
          x2 = __ldcs(xgp + 2048), x3 = __ldcs(xgp + 3072);

    for (int t = 0; t < T_SEQ; t++) {
        const uint2* hb2 = (const uint2*)g_hist16[t];

        float acc[2][2][4] = {};
        #pragma unroll 4
        for (int i = 0; i < 16; i++) {
            int kt = wk * 16 + i;             // k16-tile 0..63
            uint32_t a[2][4];
            #pragma unroll
            for (int am = 0; am < 2; am++) {
                int mb = wm * 32 + am * 16;
                uint2 u0 = __ldca(hb2 + (size_t)kt * 256 + (mb + g) * 4 + tq);
                uint2 u1 = __ldca(hb2 + (size_t)kt * 256 + (mb + 8 + g) * 4 + tq);
                a[am][0] = u0.x; a[am][1] = u1.x; a[am][2] = u0.y; a[am][3] = u1.y;
            }
            #pragma unroll
            for (int c = 0; c < 2; c++) {
                uint2 bb = Bsm[(kt * 2 + c) * 32 + lane];
                uint32_t b[2] = { bb.x, bb.y };
                mma_f16(acc[0][c], a[0], b);
                mma_f16(acc[1][c], a[1], b);
            }
        }

        // single-round reduce: each k-split warp writes its own slice
        {
            float* Gs = Gsm + wk * (64 * 20);
            #pragma unroll
            for (int am = 0; am < 2; am++) {
                int m = wm * 32 + am * 16 + g;
                #pragma unroll
                for (int c = 0; c < 2; c++) {
                    int n = c * 8 + 2 * tq;
                    *(float2*)(Gs + m * 20 + n)       = make_float2(acc[am][c][0], acc[am][c][1]);
                    *(float2*)(Gs + (m + 8) * 20 + n) = make_float2(acc[am][c][2], acc[am][c][3]);
                }
            }
        }
        __syncthreads();

        // elementwise LSTM cell: thread = (b=eb, jj=ejj); sum 4 slices
        {
            int gb = eb * 20 + ejj;           // + gate*4
            float gi = x0, gf = x1, gg = x2, go = x3;
            #pragma unroll
            for (int s = 0; s < 4; s++) {
                const float* Gs = Gsm + s * (64 * 20);
                gi += Gs[gb];
                gf += Gs[gb + 4];
                gg += Gs[gb + 8];
                go += Gs[gb + 12];
            }
            gi = 1.0f / (1.0f + __expf(-gi));
            gf = 1.0f / (1.0f + __expf(-gf));
            gg = tanhf(gg);
            go = 1.0f / (1.0f + __expf(-go));
            cst = gf * cst + gi * gg;
            float h = go * tanhf(cst);
            float hn = __shfl_xor_sync(0xffffffffu, h, 1);
            if ((ejj & 1) == 0)
                __stcg(&g_hist16[t + 1][hslot], pack2(h, hn));
            if (LAYER == 0)
                g_seq0h[((size_t)t * BATCH + eb) * HID + j0 + ejj] = __float2half_rn(h);
        }

        // grid barrier (256 CTAs, 2/SM co-resident); prefetch next xg inside
        __syncthreads();
        if (tid == 0) {
            asm volatile("red.release.gpu.global.add.u32 [%0], %1;"
                         :: "l"(&g_bar), "r"(1u) : "memory");
        }
        {
            int tn = (t + 1 < T_SEQ) ? t + 1 : t;   // clamp (last iter values unused)
            const float* xq = g_xg + ((size_t)tn * BATCH + eb) * 4096 + j0 + ejj;
            x0 = __ldcs(xq); x1 = __ldcs(xq + 1024);
            x2 = __ldcs(xq + 2048); x3 = __ldcs(xq + 3072);
        }
        if (tid == 0) {
            unsigned target = (unsigned)(t + 1) * NREC + (LAYER ? (unsigned)T_SEQ * NREC : 0u);
            unsigned v;
            do {
                asm volatile("ld.acquire.gpu.global.u32 %0, [%1];"
                             : "=r"(v) : "l"(&g_bar) : "memory");
            } while (v < target);
        }
        __syncthreads();
    }
}

// ---------------- fc head: out[b] = h_final[b][:] . Wfc + bfc ----------------
__global__ void fc_kernel(const float* __restrict__ Wfc, const float* __restrict__ bfc,
                          float* __restrict__ out)
{
    __shared__ float red[256];
    int b = blockIdx.x, tid = threadIdx.x;
    float s = 0.0f;
    for (int j = tid; j < HID; j += 256) {
        int kt = j >> 4, sub = (j >> 3) & 1, tq = (j >> 1) & 3;
        size_t idx = (size_t)kt * 512 + ((size_t)b * 4 + tq) * 2 + sub;
        unsigned u = g_hist16[T_SEQ][idx];
        __half2 hv = *reinterpret_cast<__half2*>(&u);
        float h = (j & 1) ? __high2float(hv) : __low2float(hv);
        s += h * Wfc[j];
    }
    red[tid] = s; __syncthreads();
    for (int st = 128; st > 0; st >>= 1) {
        if (tid < st) red[tid] += red[tid + st];
        __syncthreads();
    }
    if (tid == 0) out[b] = red[0] + bfc[0];
}

// ---------------- launch ----------------
extern "C" void kernel_launch(void* const* d_in, const int* in_sizes, int n_in,
                              void* d_out, int out_size)
{
    const float* x    = (const float*)d_in[0];
    const float* Wih0 = (const float*)d_in[1];
    const float* Whh0 = (const float*)d_in[2];
    const float* b0   = (const float*)d_in[3];
    const float* Wih1 = (const float*)d_in[4];
    const float* Whh1 = (const float*)d_in[5];
    const float* b1   = (const float*)d_in[6];
    const float* Wfc  = (const float*)d_in[7];
    const float* bfc  = (const float*)d_in[8];
    float* out = (float*)d_out;

    const size_t rec_smem = 32768 + (size_t)4 * 64 * 20 * 4;   // 53248 B (2 CTAs/SM)
    static int attr_done = 0;
    if (!attr_done) {
        cudaFuncSetAttribute(lstm_rec<0>, cudaFuncAttributeMaxDynamicSharedMemorySize, (int)rec_smem);
        cudaFuncSetAttribute(lstm_rec<1>, cudaFuncAttributeMaxDynamicSharedMemorySize, (int)rec_smem);
        attr_done = 1;
    }

    reset_kernel<<<64, 256>>>();
    f2h_kernel<0><<<256, 256>>>(Wih0, 4096 * DIN);
    f2h_kernel<1><<<256, 256>>>(Wih1, 4096 * HID);
    f2h_kernel<2><<<256, 256>>>(x, BATCH * T_SEQ * DIN);
    gemm_xg<0><<<dim3(32, T_SEQ / 2), 256>>>(b0, DIN);
    lstm_rec<0><<<NREC, 256, rec_smem>>>(Whh0);
    gemm_xg<1><<<dim3(32, T_SEQ / 2), 256>>>(b1, HID);
    lstm_rec<1><<<NREC, 256, rec_smem>>>(Whh1);   // barrier counter continues from T_SEQ*NREC
    fc_kernel<<<BATCH, 256>>>(Wfc, bfc, out);
}

// round 17
// speedup vs baseline: 1.0110x; 1.0110x over previous
#include <cuda_runtime.h>
#include <cuda_fp16.h>
#include <cstdint>
#include <cstddef>

#define T_SEQ 512
#define BATCH 64
#define DIN   256
#define HID   1024
#define NREC  256   // recurrence CTAs: 128 hidden-groups x 2 batch-halves (2 per SM)

// ---------------- static scratch (no allocations) ----------------
__device__ __align__(16) float  g_xg[(size_t)T_SEQ * BATCH * 4096];    // [t][b][4H] fp32
__device__ __align__(16) __half g_seq0h[(size_t)T_SEQ * BATCH * HID];  // [t][b][k] fp16
__device__ __align__(16) __half g_x16[(size_t)BATCH * T_SEQ * DIN];    // x as fp16
__device__ __align__(16) __half g_w0_16[(size_t)4096 * DIN];           // Wih0 fp16
__device__ __align__(16) __half g_w1_16[(size_t)4096 * HID];           // Wih1 fp16
// h HISTORY: step t's h at g_hist16[t]. fp16 pairs, PAIR-INTERLEAVED m16n8k16
// fragment order: u32 slot = kt*512 + (m*4 + tq)*2 + sub
//   (k = kt*16 + sub*8 + tq*2 + {lo,hi}, m = absolute batch index)
__device__ __align__(16) unsigned g_hist16[T_SEQ + 1][(HID / 16) * 512];
__device__ unsigned g_bar;

// ---------------- helpers ----------------
__device__ __forceinline__ unsigned pack2(float x, float y) {
    __half2 h = __floats2half2_rn(x, y);
    return *reinterpret_cast<unsigned*>(&h);
}

__device__ __forceinline__ void mma_f16(float c[4], const uint32_t a[4], const uint32_t b[2]) {
    asm volatile(
        "mma.sync.aligned.m16n8k16.row.col.f32.f16.f16.f32 "
        "{%0,%1,%2,%3}, {%4,%5,%6,%7}, {%8,%9}, {%0,%1,%2,%3};"
        : "+f"(c[0]), "+f"(c[1]), "+f"(c[2]), "+f"(c[3])
        : "r"(a[0]), "r"(a[1]), "r"(a[2]), "r"(a[3]), "r"(b[0]), "r"(b[1]));
}

// ---------------- reset: zero h[0] + grid barrier ----------------
__global__ void reset_kernel() {
    int tid = blockIdx.x * blockDim.x + threadIdx.x;
    for (int i = tid; i < (HID / 16) * 512; i += gridDim.x * blockDim.x)
        g_hist16[0][i] = 0u;
    if (tid == 0) g_bar = 0u;
}

// ---------------- one-time fp32 -> fp16 conversion ----------------
template<int WHICH>
__global__ void f2h_kernel(const float* __restrict__ src, int n) {
    __half* dst = (WHICH == 0) ? g_w0_16 : (WHICH == 1) ? g_w1_16 : g_x16;
    int tid = blockIdx.x * blockDim.x + threadIdx.x;
    for (int i = tid; i < n; i += gridDim.x * blockDim.x)
        dst[i] = __float2half_rn(src[i]);
}

// ---------------- xg GEMM (fp16 inputs, M=128: 2 timesteps per CTA) ----------------
template<int AMODE>
__global__ __launch_bounds__(256) void gemm_xg(const float* __restrict__ bias, int K)
{
    __shared__ __align__(16) unsigned Ash[128 * 20];
    __shared__ __align__(16) unsigned Bsh[128 * 20];

    const __half* A16 = (AMODE == 0) ? g_x16 : g_seq0h;
    const __half* W16 = (AMODE == 0) ? g_w0_16 : g_w1_16;

    const int tid = threadIdx.x, lane = tid & 31, w = tid >> 5;
    const int wm = w & 1, wn = w >> 1;
    const int t0 = blockIdx.y * 2, n0 = blockIdx.x * 128;
    const int g = lane >> 2, tq = lane & 3;

    float acc[4][4][4] = {};

    const int nchunk = K / 32;
    for (int kc = 0; kc < nchunk; kc++) {
        int k0 = kc * 32;
        __syncthreads();
        #pragma unroll
        for (int i = 0; i < 2; i++) {
            int fi = tid + i * 256; int r = fi >> 2, q = fi & 3;
            int tl = r >> 6, b = r & 63;
            size_t off = (AMODE == 0)
                ? ((size_t)b * T_SEQ + t0 + tl) * DIN + k0 + q * 8
                : ((size_t)(t0 + tl) * BATCH + b) * HID + k0 + q * 8;
            uint4 v = *(const uint4*)(A16 + off);
            *(uint4*)(Ash + r * 20 + q * 4) = v;
        }
        #pragma unroll
        for (int i = 0; i < 2; i++) {
            int fi = tid + i * 256; int r = fi >> 2, q = fi & 3;
            uint4 v = *(const uint4*)(W16 + (size_t)(n0 + r) * K + k0 + q * 8);
            *(uint4*)(Bsh + r * 20 + q * 4) = v;
        }
        __syncthreads();
        #pragma unroll
        for (int kt = 0; kt < 2; kt++) {
            uint32_t a[4][4];
            #pragma unroll
            for (int am = 0; am < 4; am++) {
                int mb = wm * 64 + am * 16;
                a[am][0] = Ash[(mb + g) * 20 + kt * 8 + tq];
                a[am][1] = Ash[(mb + 8 + g) * 20 + kt * 8 + tq];
                a[am][2] = Ash[(mb + g) * 20 + kt * 8 + tq + 4];
                a[am][3] = Ash[(mb + 8 + g) * 20 + kt * 8 + tq + 4];
            }
            #pragma unroll
            for (int c = 0; c < 4; c++) {
                int nb = (wn * 4 + c) * 8;
                uint32_t b[2];
                b[0] = Bsh[(nb + g) * 20 + kt * 8 + tq];
                b[1] = Bsh[(nb + g) * 20 + kt * 8 + tq + 4];
                #pragma unroll
                for (int am = 0; am < 4; am++) mma_f16(acc[am][c], a[am], b);
            }
        }
    }
    #pragma unroll
    for (int am = 0; am < 4; am++) {
        int m = wm * 64 + am * 16 + g;
        int tl = m >> 6, b = m & 63;
        #pragma unroll
        for (int c = 0; c < 4; c++) {
            int n = n0 + (wn * 4 + c) * 8 + 2 * tq;
            float2 bi = *(const float2*)(bias + n);
            *(float2*)(g_xg + ((size_t)(t0 + tl) * BATCH + b) * 4096 + n) =
                make_float2(acc[am][c][0] + bi.x, acc[am][c][1] + bi.y);
            *(float2*)(g_xg + ((size_t)(t0 + tl) * BATCH + b + 8) * 4096 + n) =
                make_float2(acc[am][c][2] + bi.x, acc[am][c][3] + bi.y);
        }
    }
}

// ---------------- persistent LSTM recurrence (fp16 mma, M=32 tiling) ----------------
// 256 CTAs x 256 threads. CTA bx: hidden-group hg = bx>>1 (8 hidden units -> 32 gate
// rows), batch half bhalf = bx&1 (M=32 batches). Per-CTA h read = 64 KB/step
// -> chip h traffic 16 MB/step (half of the old M=64 tiling).
// 8 warps = wn(2: c-groups of 2 n8-tiles) x wk(4: k-split of 16 k16-tiles each).
template<int LAYER>
__global__ __launch_bounds__(256, 2) void lstm_rec(const float* __restrict__ Whh)
{
    extern __shared__ __align__(16) char smraw[];
    uint2* Bsm = (uint2*)smraw;                       // 64kt x 4c x 32lane uint2 = 64 KB
    float* Gsm = (float*)(smraw + 65536);             // 4 slices x 32 x 36

    const int tid = threadIdx.x, lane = tid & 31, w = tid >> 5;
    const int g = lane >> 2, tq = lane & 3;
    const int wn = w & 1;            // c-group (2 n8-tiles each)
    const int wk = w >> 1;           // 0..3 : k-split (16 k16-tiles each)
    const int bx = blockIdx.x;
    const int hg = bx >> 1;          // hidden group 0..127
    const int bhalf = bx & 1;        // batch half
    const int j0 = hg * 8;

    // load 32 weight rows (nrow = gate*8 + jj) -> SMEM in B-fragment order
    unsigned* Wsm32 = (unsigned*)smraw;
    #pragma unroll
    for (int i = 0; i < 32; i++) {
        int fi = tid + i * 256;               // float4 index 0..8191
        int r = fi >> 8, c4 = fi & 255;       // r = nrow = gate*8+jj ; k0 = c4*4
        int gate = r >> 3, jj = r & 7;
        float4 v = *(const float4*)(Whh + (size_t)(gate * HID + j0 + jj) * HID + c4 * 4);
        int kt = c4 >> 2, sub = (c4 >> 1) & 1, tq0 = (c4 & 1) * 2;
        int base = ((kt * 4 + gate) * 32 + jj * 4 + tq0) * 2 + sub;
        Wsm32[base]     = pack2(v.x, v.y);
        Wsm32[base + 2] = pack2(v.z, v.w);
    }

    // elementwise mapping: 256 threads = 32 local batches x 8 jj
    const int ejj = tid & 7, bl = tid >> 3;
    const int eb = bhalf * 32 + bl;           // absolute batch
    // producer u32 slot for k = j0 + ejj (threads pair over ejj parity):
    const int ktp = hg >> 1, subp = hg & 1, tqp = ejj >> 1;
    const size_t hslot = (size_t)ktp * 512 + ((size_t)eb * 4 + tqp) * 2 + subp;
    float cst = 0.0f;
    __syncthreads();

    // prefetch xg for t=0
    const float* xgp = g_xg + (size_t)eb * 4096 + j0 + ejj;
    float x0 = __ldcs(xgp), x1 = __ldcs(xgp + 1024),
          x2 = __ldcs(xgp + 2048), x3 = __ldcs(xgp + 3072);

    for (int t = 0; t < T_SEQ; t++) {
        const uint2* hb2 = (const uint2*)g_hist16[t];

        float acc[2][2][4] = {};
        #pragma unroll 4
        for (int i = 0; i < 16; i++) {
            int kt = wk * 16 + i;             // k16-tile 0..63
            uint32_t a[2][4];
            #pragma unroll
            for (int am = 0; am < 2; am++) {
                int mb = bhalf * 32 + am * 16;
                uint2 u0 = __ldcg(hb2 + (size_t)kt * 256 + (mb + g) * 4 + tq);
                uint2 u1 = __ldcg(hb2 + (size_t)kt * 256 + (mb + 8 + g) * 4 + tq);
                a[am][0] = u0.x; a[am][1] = u1.x; a[am][2] = u0.y; a[am][3] = u1.y;
            }
            #pragma unroll
            for (int c = 0; c < 2; c++) {
                uint2 bb = Bsm[(kt * 4 + wn * 2 + c) * 32 + lane];
                uint32_t b[2] = { bb.x, bb.y };
                mma_f16(acc[0][c], a[0], b);
                mma_f16(acc[1][c], a[1], b);
            }
        }

        // single-round reduce: each k-split warp writes its own slice (32 x 36)
        {
            float* Gs = Gsm + wk * (32 * 36);
            #pragma unroll
            for (int am = 0; am < 2; am++) {
                int m = am * 16 + g;          // local batch row 0..31
                #pragma unroll
                for (int c = 0; c < 2; c++) {
                    int n = (wn * 2 + c) * 8 + 2 * tq;
                    *(float2*)(Gs + m * 36 + n)       = make_float2(acc[am][c][0], acc[am][c][1]);
                    *(float2*)(Gs + (m + 8) * 36 + n) = make_float2(acc[am][c][2], acc[am][c][3]);
                }
            }
        }
        __syncthreads();

        // elementwise LSTM cell: thread = (bl, ejj); sum 4 k-slices
        {
            int gb = bl * 36 + ejj;
            float gi = x0, gf = x1, gg = x2, go = x3;
            #pragma unroll
            for (int s = 0; s < 4; s++) {
                const float* Gs = Gsm + s * (32 * 36);
                gi += Gs[gb];
                gf += Gs[gb + 8];
                gg += Gs[gb + 16];
                go += Gs[gb + 24];
            }
            gi = 1.0f / (1.0f + __expf(-gi));
            gf = 1.0f / (1.0f + __expf(-gf));
            gg = tanhf(gg);
            go = 1.0f / (1.0f + __expf(-go));
            cst = gf * cst + gi * gg;
            float h = go * tanhf(cst);
            float hn = __shfl_xor_sync(0xffffffffu, h, 1);
            if ((ejj & 1) == 0)
                __stcg(&g_hist16[t + 1][hslot], pack2(h, hn));
            if (LAYER == 0)
                g_seq0h[((size_t)t * BATCH + eb) * HID + j0 + ejj] = __float2half_rn(h);
        }

        // grid barrier (256 CTAs, 2/SM co-resident); prefetch next xg inside
        __syncthreads();
        if (tid == 0) {
            asm volatile("red.release.gpu.global.add.u32 [%0], %1;"
                         :: "l"(&g_bar), "r"(1u) : "memory");
        }
        {
            int tn = (t + 1 < T_SEQ) ? t + 1 : t;   // clamp (last iter values unused)
            const float* xq = g_xg + ((size_t)tn * BATCH + eb) * 4096 + j0 + ejj;
            x0 = __ldcs(xq); x1 = __ldcs(xq + 1024);
            x2 = __ldcs(xq + 2048); x3 = __ldcs(xq + 3072);
        }
        if (tid == 0) {
            unsigned target = (unsigned)(t + 1) * NREC + (LAYER ? (unsigned)T_SEQ * NREC : 0u);
            unsigned v;
            do {
                asm volatile("ld.acquire.gpu.global.u32 %0, [%1];"
                             : "=r"(v) : "l"(&g_bar) : "memory");
            } while (v < target);
        }
        __syncthreads();
    }
}

// ---------------- fc head: out[b] = h_final[b][:] . Wfc + bfc ----------------
__global__ void fc_kernel(const float* __restrict__ Wfc, const float* __restrict__ bfc,
                          float* __restrict__ out)
{
    __shared__ float red[256];
    int b = blockIdx.x, tid = threadIdx.x;
    float s = 0.0f;
    for (int j = tid; j < HID; j += 256) {
        int kt = j >> 4, sub = (j >> 3) & 1, tq = (j >> 1) & 3;
        size_t idx = (size_t)kt * 512 + ((size_t)b * 4 + tq) * 2 + sub;
        unsigned u = g_hist16[T_SEQ][idx];
        __half2 hv = *reinterpret_cast<__half2*>(&u);
        float h = (j & 1) ? __high2float(hv) : __low2float(hv);
        s += h * Wfc[j];
    }
    red[tid] = s; __syncthreads();
    for (int st = 128; st > 0; st >>= 1) {
        if (tid < st) red[tid] += red[tid + st];
        __syncthreads();
    }
    if (tid == 0) out[b] = red[0] + bfc[0];
}

// ---------------- launch ----------------
extern "C" void kernel_launch(void* const* d_in, const int* in_sizes, int n_in,
                              void* d_out, int out_size)
{
    const float* x    = (const float*)d_in[0];
    const float* Wih0 = (const float*)d_in[1];
    const float* Whh0 = (const float*)d_in[2];
    const float* b0   = (const float*)d_in[3];
    const float* Wih1 = (const float*)d_in[4];
    const float* Whh1 = (const float*)d_in[5];
    const float* b1   = (const float*)d_in[6];
    const float* Wfc  = (const float*)d_in[7];
    const float* bfc  = (const float*)d_in[8];
    float* out = (float*)d_out;

    const size_t rec_smem = 65536 + (size_t)4 * 32 * 36 * 4;   // 83968 B (2 CTAs/SM)
    static int attr_done = 0;
    if (!attr_done) {
        cudaFuncSetAttribute(lstm_rec<0>, cudaFuncAttributeMaxDynamicSharedMemorySize, (int)rec_smem);
        cudaFuncSetAttribute(lstm_rec<1>, cudaFuncAttributeMaxDynamicSharedMemorySize, (int)rec_smem);
        attr_done = 1;
    }

    reset_kernel<<<64, 256>>>();
    f2h_kernel<0><<<256, 256>>>(Wih0, 4096 * DIN);
    f2h_kernel<1><<<256, 256>>>(Wih1, 4096 * HID);
    f2h_kernel<2><<<256, 256>>>(x, BATCH * T_SEQ * DIN);
    gemm_xg<0><<<dim3(32, T_SEQ / 2), 256>>>(b0, DIN);
    lstm_rec<0><<<NREC, 256, rec_smem>>>(Whh0);
    gemm_xg<1><<<dim3(32, T_SEQ / 2), 256>>>(b1, HID);
    lstm_rec<1><<<NREC, 256, rec_smem>>>(Whh1);   // barrier counter continues from T_SEQ*NREC
    fc_kernel<<<BATCH, 256>>>(Wfc, bfc, out);
}